// round 6
// baseline (speedup 1.0000x reference)
#include <cuda_runtime.h>

#define B_POINTS 131072
#define HALF     65536
#define NSTEP    64
#define NTHREADS 64
#define NBLOCKS  (HALF / NTHREADS)   // 1024

typedef unsigned long long u64;

// ---- f32x2 packed helpers (sm_103a FFMA2 path, PTX-only) ----
__device__ __forceinline__ u64 f2fma(u64 a, u64 b, u64 c) {
    u64 d;
    asm("fma.rn.f32x2 %0, %1, %2, %3;" : "=l"(d) : "l"(a), "l"(b), "l"(c));
    return d;
}
__device__ __forceinline__ u64 pack2(float lo, float hi) {
    u64 d;
    asm("mov.b64 %0, {%1, %2};" : "=l"(d) : "f"(lo), "f"(hi));
    return d;
}
__device__ __forceinline__ void unpack2(u64 v, float& lo, float& hi) {
    asm("mov.b64 {%0, %1}, %2;" : "=f"(lo), "=f"(hi) : "l"(v));
}
__device__ __forceinline__ u64 f2relu(u64 v) {
    float lo, hi;
    unpack2(v, lo, hi);
    return pack2(fmaxf(lo, 0.0f), fmaxf(hi, 0.0f));   // FMNMX = alu pipe
}

__global__ __launch_bounds__(NTHREADS, 10)
void ode_rk4_kernel(const float* __restrict__ x,
                    const float* __restrict__ samples,
                    const float* __restrict__ w1, const float* __restrict__ b1,
                    const float* __restrict__ w2, const float* __restrict__ b2,
                    const float* __restrict__ w3, const float* __restrict__ b3,
                    const float* __restrict__ w_out, const float* __restrict__ b_out,
                    float* __restrict__ out)
{
    // sw1d[2i]   = (dup w1[0][i], dup w1[1][i])       -- layer1 packed (A,B), dup'd
    // sw1d[2i+1] = (dup w1[2][i], dup b1[i])
    // sw2v: w2 row-major verbatim (UNdup); ulonglong2 = 4 consecutive w2[i][j]
    // sb2v: b2 verbatim
    // sw3p[o*16+j2] = (w3[2j2][o], w3[2j2+1][o])      -- transposed pairs, undup
    __shared__ ulonglong2 sw1d[64];
    __shared__ ulonglong2 sw2v[32 * 8];
    __shared__ ulonglong2 sb2v[8];
    __shared__ u64        sw3p[48];
    __shared__ float      sb3s[3];
    __shared__ float      swo[4];
    __shared__ u64        scs[4], sca[4], ssx;   // packed RK4 stage coeffs
    __shared__ float      sdt;
    __shared__ int        ssidx[8];

    const int t = threadIdx.x;

    if (t < 32) {
        float a = w1[0 * 32 + t], b = w1[1 * 32 + t], c = w1[2 * 32 + t], d = b1[t];
        sw1d[2 * t]     = make_ulonglong2(pack2(a, a), pack2(b, b));
        sw1d[2 * t + 1] = make_ulonglong2(pack2(c, c), pack2(d, d));
    }
    for (int i = t; i < 1024; i += NTHREADS)
        ((float*)sw2v)[i] = w2[i];
    for (int i = t; i < 96; i += NTHREADS) {
        int o = i >> 5, j = i & 31;
        ((float*)sw3p)[o * 32 + j] = w3[j * 3 + o];
    }
    if (t < 32) ((float*)sb2v)[t] = b2[t];
    if (t < 3)  { sb3s[t] = b3[t]; swo[t] = w_out[t]; }
    if (t == 3) swo[3] = b_out[0];
    if (t == 0) {
        float mx = samples[0];
        #pragma unroll
        for (int s = 1; s < 8; s++) mx = fmaxf(mx, samples[s]);
        float dt = mx / (float)NSTEP;
        sdt = dt;
        scs[0] = pack2(1.f, 1.f); scs[1] = pack2(2.f, 2.f);
        scs[2] = pack2(2.f, 2.f); scs[3] = pack2(1.f, 1.f);
        float h = 0.5f * dt;
        sca[0] = pack2(h, h); sca[1] = pack2(h, h);
        sca[2] = pack2(dt, dt); sca[3] = pack2(0.f, 0.f);
        float sx = dt / 6.0f;
        ssx = pack2(sx, sx);
    }
    __syncthreads();
    if (t < 8) {
        int ii = (int)(rintf(samples[t] / sdt)) - 1;
        ssidx[t] = min(max(ii, 0), NSTEP - 1);
    }
    __syncthreads();

    u64 emit_mask = 0ull;
    #pragma unroll
    for (int s = 0; s < 8; s++) emit_mask |= 1ull << ssidx[s];

    const float bq0 = sb3s[0], bq1 = sb3s[1], bq2 = sb3s[2];

    const int g  = blockIdx.x * NTHREADS + t;
    const int p0 = g, p1 = g + HALF;

    // Packed state: y0 = (yA0, yB0) etc.
    u64 y0 = pack2(x[p0 * 3 + 0], x[p1 * 3 + 0]);
    u64 y1 = pack2(x[p0 * 3 + 1], x[p1 * 3 + 1]);
    u64 y2 = pack2(x[p0 * 3 + 2], x[p1 * 3 + 2]);

    // MLP 3->32->32->3 for the packed point pair.
    // L1: packed (A,B) with dup'd weights; L2/L3: neuron-pair packing, undup'd.
    auto mlp = [&](u64 a0, u64 a1, u64 a2, u64& k0, u64& k1, u64& k2) {
        u64 hA[16], hB[16];
        #pragma unroll
        for (int q = 0; q < 8; q++) {
            ulonglong2 b = sb2v[q];
            hA[q * 2] = b.x; hA[q * 2 + 1] = b.y;
            hB[q * 2] = b.x; hB[q * 2 + 1] = b.y;
        }
        #pragma unroll 2
        for (int i = 0; i < 32; i++) {
            ulonglong2 wp = sw1d[2 * i];
            ulonglong2 wq = sw1d[2 * i + 1];
            u64 hp = f2fma(a0, wp.x, wq.y);
            hp = f2fma(a1, wp.y, hp);
            hp = f2fma(a2, wq.x, hp);
            float h1A, h1B;
            unpack2(hp, h1A, h1B);
            h1A = fmaxf(h1A, 0.0f);
            h1B = fmaxf(h1B, 0.0f);
            u64 dA = pack2(h1A, h1A);
            u64 dB = pack2(h1B, h1B);
            #pragma unroll
            for (int q = 0; q < 8; q++) {
                ulonglong2 w = sw2v[i * 8 + q];
                hA[q * 2]     = f2fma(dA, w.x, hA[q * 2]);
                hA[q * 2 + 1] = f2fma(dA, w.y, hA[q * 2 + 1]);
                hB[q * 2]     = f2fma(dB, w.x, hB[q * 2]);
                hB[q * 2 + 1] = f2fma(dB, w.y, hB[q * 2 + 1]);
            }
        }
        u64 z = pack2(0.0f, 0.0f);
        u64 c0A = z, c1A = z, c2A = z, c0B = z, c1B = z, c2B = z;
        #pragma unroll
        for (int j2 = 0; j2 < 16; j2++) {
            u64 u0 = sw3p[j2];
            u64 u1 = sw3p[16 + j2];
            u64 u2 = sw3p[32 + j2];
            u64 rA = f2relu(hA[j2]);
            u64 rB = f2relu(hB[j2]);
            c0A = f2fma(rA, u0, c0A); c1A = f2fma(rA, u1, c1A); c2A = f2fma(rA, u2, c2A);
            c0B = f2fma(rB, u0, c0B); c1B = f2fma(rB, u1, c1B); c2B = f2fma(rB, u2, c2B);
        }
        float lo, hi, lo2, hi2;
        unpack2(c0A, lo, hi); unpack2(c0B, lo2, hi2);
        k0 = pack2(bq0 + lo + hi, bq0 + lo2 + hi2);
        unpack2(c1A, lo, hi); unpack2(c1B, lo2, hi2);
        k1 = pack2(bq1 + lo + hi, bq1 + lo2 + hi2);
        unpack2(c2A, lo, hi); unpack2(c2B, lo2, hi2);
        k2 = pack2(bq2 + lo + hi, bq2 + lo2 + hi2);
    };

    #pragma unroll 1
    for (int step = 0; step < NSTEP; step++) {
        u64 z = pack2(0.f, 0.f);
        u64 s0 = z, s1 = z, s2 = z;
        u64 a0 = y0, a1 = y1, a2 = y2;

        #pragma unroll 1
        for (int st = 0; st < 4; st++) {
            u64 k0, k1, k2;
            mlp(a0, a1, a2, k0, k1, k2);
            u64 cs = scs[st];
            u64 ca = sca[st];
            s0 = f2fma(k0, cs, s0); s1 = f2fma(k1, cs, s1); s2 = f2fma(k2, cs, s2);
            a0 = f2fma(k0, ca, y0); a1 = f2fma(k1, ca, y1); a2 = f2fma(k2, ca, y2);
        }
        u64 sx2 = ssx;
        y0 = f2fma(s0, sx2, y0); y1 = f2fma(s1, sx2, y1); y2 = f2fma(s2, sx2, y2);

        if ((emit_mask >> step) & 1ull) {
            float uA0, uB0, uA1, uB1, uA2, uB2;
            unpack2(y0, uA0, uB0); unpack2(y1, uA1, uB1); unpack2(y2, uA2, uB2);
            float wo0 = swo[0], wo1 = swo[1], wo2 = swo[2], bo = swo[3];
            float oA = fmaf(uA0, wo0, fmaf(uA1, wo1, fmaf(uA2, wo2, bo)));
            float oB = fmaf(uB0, wo0, fmaf(uB1, wo1, fmaf(uB2, wo2, bo)));
            #pragma unroll 1
            for (int s = 0; s < 8; s++) {
                if (ssidx[s] == step) {
                    out[s * B_POINTS + p0] = oA;
                    out[s * B_POINTS + p1] = oB;
                }
            }
        }
    }
}

extern "C" void kernel_launch(void* const* d_in, const int* in_sizes, int n_in,
                              void* d_out, int out_size)
{
    const float* x      = (const float*)d_in[0];
    const float* samples= (const float*)d_in[1];
    const float* w1     = (const float*)d_in[2];
    const float* b1     = (const float*)d_in[3];
    const float* w2     = (const float*)d_in[4];
    const float* b2     = (const float*)d_in[5];
    const float* w3     = (const float*)d_in[6];
    const float* b3     = (const float*)d_in[7];
    const float* w_out  = (const float*)d_in[8];
    const float* b_out  = (const float*)d_in[9];
    float* out = (float*)d_out;

    ode_rk4_kernel<<<NBLOCKS, NTHREADS>>>(x, samples, w1, b1, w2, b2, w3, b3,
                                          w_out, b_out, out);
}

// round 9
// speedup vs baseline: 1.2796x; 1.2796x over previous
#include <cuda_runtime.h>

#define B_POINTS 131072
#define HALF     65536
#define NSTEP    64
#define NTHREADS 64
#define NBLOCKS  (HALF / NTHREADS)   // 1024

typedef unsigned long long u64;

// ---- f32x2 packed helpers (sm_103a FFMA2 path, PTX-only) ----
__device__ __forceinline__ u64 f2fma(u64 a, u64 b, u64 c) {
    u64 d;
    asm("fma.rn.f32x2 %0, %1, %2, %3;" : "=l"(d) : "l"(a), "l"(b), "l"(c));
    return d;
}
__device__ __forceinline__ u64 pack2(float lo, float hi) {
    u64 d;
    asm("mov.b64 %0, {%1, %2};" : "=l"(d) : "f"(lo), "f"(hi));
    return d;
}
__device__ __forceinline__ void unpack2(u64 v, float& lo, float& hi) {
    asm("mov.b64 {%0, %1}, %2;" : "=f"(lo), "=f"(hi) : "l"(v));
}
__device__ __forceinline__ u64 f2relu(u64 v) {
    float lo, hi;
    unpack2(v, lo, hi);
    return pack2(fmaxf(lo, 0.0f), fmaxf(hi, 0.0f));   // FMNMX = alu pipe
}

__global__ __launch_bounds__(NTHREADS, 7)   // 146-reg budget; grid fills only 6.92/SM
void ode_rk4_kernel(const float* __restrict__ x,
                    const float* __restrict__ samples,
                    const float* __restrict__ w1, const float* __restrict__ b1,
                    const float* __restrict__ w2, const float* __restrict__ b2,
                    const float* __restrict__ w3, const float* __restrict__ b3,
                    const float* __restrict__ w_out, const float* __restrict__ b_out,
                    float* __restrict__ out)
{
    // Neuron-pair packing: NO weight duplication.
    // sw1v[i] = (w1[0][i], w1[1][i], w1[2][i], b1[i])        -- 1 LDS.128 per i
    // sw2v:  w2 row-major verbatim; ulonglong2 = 4 consecutive w2[i][j] = 2 FFMA2 operands
    // sb2v:  b2 verbatim (consecutive floats form the neuron pairs)
    // sw3p[o*16+j2] = (w3[2*j2][o], w3[2*j2+1][o])           -- transposed pairs
    __shared__ float4     sw1v[32];
    __shared__ ulonglong2 sw2v[32 * 8];
    __shared__ ulonglong2 sb2v[8];
    __shared__ u64        sw3p[48];
    __shared__ float      sb3s[3];
    __shared__ float      swo[4];
    __shared__ float      sdt;
    __shared__ int        ssidx[8];

    const int t = threadIdx.x;

    for (int i4 = t; i4 < 128; i4 += NTHREADS) {
        int i = i4 >> 2, d = i4 & 3;
        ((float*)sw1v)[i4] = (d < 3) ? w1[d * 32 + i] : b1[i];
    }
    for (int i = t; i < 1024; i += NTHREADS)
        ((float*)sw2v)[i] = w2[i];
    for (int i = t; i < 96; i += NTHREADS) {
        int o = i >> 5, j = i & 31;
        ((float*)sw3p)[o * 32 + j] = w3[j * 3 + o];
    }
    if (t < 32) ((float*)sb2v)[t] = b2[t];
    if (t < 3)  { sb3s[t] = b3[t]; swo[t] = w_out[t]; }
    if (t == 3) swo[3] = b_out[0];
    if (t == 0) {
        float mx = samples[0];
        #pragma unroll
        for (int s = 1; s < 8; s++) mx = fmaxf(mx, samples[s]);
        sdt = mx / (float)NSTEP;
    }
    __syncthreads();
    if (t < 8) {
        int ii = (int)(rintf(samples[t] / sdt)) - 1;
        ssidx[t] = min(max(ii, 0), NSTEP - 1);
    }
    __syncthreads();

    u64 emit_mask = 0ull;
    #pragma unroll
    for (int s = 0; s < 8; s++) emit_mask |= 1ull << ssidx[s];

    const float dt  = sdt;
    const float hdt = 0.5f * dt;
    const float sx  = dt / 6.0f;
    const float wo0 = swo[0], wo1 = swo[1], wo2 = swo[2], bo = swo[3];
    const float bq0 = sb3s[0], bq1 = sb3s[1], bq2 = sb3s[2];

    const int g  = blockIdx.x * NTHREADS + t;
    const int p0 = g, p1 = g + HALF;

    float yA0 = x[p0 * 3 + 0], yA1 = x[p0 * 3 + 1], yA2 = x[p0 * 3 + 2];
    float yB0 = x[p1 * 3 + 0], yB1 = x[p1 * 3 + 1], yB2 = x[p1 * 3 + 2];

    // MLP 3->32->32->3 for two points. Layer1 fused into the i-loop (scalar),
    // layer2 accumulates 16 neuron-pairs per point, layer3 folds pairs.
    auto mlp = [&](float aA0, float aA1, float aA2,
                   float aB0, float aB1, float aB2,
                   float& kA0, float& kA1, float& kA2,
                   float& kB0, float& kB1, float& kB2) {
        u64 hA[16], hB[16];
        #pragma unroll
        for (int q = 0; q < 8; q++) {
            ulonglong2 b = sb2v[q];
            hA[q * 2] = b.x; hA[q * 2 + 1] = b.y;
            hB[q * 2] = b.x; hB[q * 2 + 1] = b.y;
        }
        #pragma unroll 8
        for (int i = 0; i < 32; i++) {
            float4 wv = sw1v[i];
            float h1A = wv.w;
            h1A = fmaf(aA0, wv.x, h1A);
            h1A = fmaf(aA1, wv.y, h1A);
            h1A = fmaf(aA2, wv.z, h1A);
            h1A = fmaxf(h1A, 0.0f);
            float h1B = wv.w;
            h1B = fmaf(aB0, wv.x, h1B);
            h1B = fmaf(aB1, wv.y, h1B);
            h1B = fmaf(aB2, wv.z, h1B);
            h1B = fmaxf(h1B, 0.0f);
            u64 dA = pack2(h1A, h1A);
            u64 dB = pack2(h1B, h1B);
            #pragma unroll
            for (int q = 0; q < 8; q++) {
                ulonglong2 w = sw2v[i * 8 + q];
                hA[q * 2]     = f2fma(dA, w.x, hA[q * 2]);
                hA[q * 2 + 1] = f2fma(dA, w.y, hA[q * 2 + 1]);
                hB[q * 2]     = f2fma(dB, w.x, hB[q * 2]);
                hB[q * 2 + 1] = f2fma(dB, w.y, hB[q * 2 + 1]);
            }
        }
        u64 z = pack2(0.0f, 0.0f);
        u64 c0A = z, c1A = z, c2A = z, c0B = z, c1B = z, c2B = z;
        #pragma unroll
        for (int j2 = 0; j2 < 16; j2++) {
            u64 u0 = sw3p[j2];
            u64 u1 = sw3p[16 + j2];
            u64 u2 = sw3p[32 + j2];
            u64 rA = f2relu(hA[j2]);
            u64 rB = f2relu(hB[j2]);
            c0A = f2fma(rA, u0, c0A); c1A = f2fma(rA, u1, c1A); c2A = f2fma(rA, u2, c2A);
            c0B = f2fma(rB, u0, c0B); c1B = f2fma(rB, u1, c1B); c2B = f2fma(rB, u2, c2B);
        }
        float lo, hi;
        unpack2(c0A, lo, hi); kA0 = bq0 + lo + hi;
        unpack2(c1A, lo, hi); kA1 = bq1 + lo + hi;
        unpack2(c2A, lo, hi); kA2 = bq2 + lo + hi;
        unpack2(c0B, lo, hi); kB0 = bq0 + lo + hi;
        unpack2(c1B, lo, hi); kB1 = bq1 + lo + hi;
        unpack2(c2B, lo, hi); kB2 = bq2 + lo + hi;
    };

    #pragma unroll 1
    for (int step = 0; step < NSTEP; step++) {
        float sA0 = 0.f, sA1 = 0.f, sA2 = 0.f;
        float sB0 = 0.f, sB1 = 0.f, sB2 = 0.f;
        float aA0 = yA0, aA1 = yA1, aA2 = yA2;
        float aB0 = yB0, aB1 = yB1, aB2 = yB2;

        #pragma unroll 1
        for (int st = 0; st < 4; st++) {
            float kA0, kA1, kA2, kB0, kB1, kB2;
            mlp(aA0, aA1, aA2, aB0, aB1, aB2, kA0, kA1, kA2, kB0, kB1, kB2);
            float cs = (st == 1 || st == 2) ? 2.0f : 1.0f;
            float ca = (st == 2) ? dt : hdt;
            sA0 = fmaf(kA0, cs, sA0); sA1 = fmaf(kA1, cs, sA1); sA2 = fmaf(kA2, cs, sA2);
            sB0 = fmaf(kB0, cs, sB0); sB1 = fmaf(kB1, cs, sB1); sB2 = fmaf(kB2, cs, sB2);
            aA0 = fmaf(kA0, ca, yA0); aA1 = fmaf(kA1, ca, yA1); aA2 = fmaf(kA2, ca, yA2);
            aB0 = fmaf(kB0, ca, yB0); aB1 = fmaf(kB1, ca, yB1); aB2 = fmaf(kB2, ca, yB2);
        }
        yA0 = fmaf(sA0, sx, yA0); yA1 = fmaf(sA1, sx, yA1); yA2 = fmaf(sA2, sx, yA2);
        yB0 = fmaf(sB0, sx, yB0); yB1 = fmaf(sB1, sx, yB1); yB2 = fmaf(sB2, sx, yB2);

        if ((emit_mask >> step) & 1ull) {
            float oA = fmaf(yA0, wo0, fmaf(yA1, wo1, fmaf(yA2, wo2, bo)));
            float oB = fmaf(yB0, wo0, fmaf(yB1, wo1, fmaf(yB2, wo2, bo)));
            #pragma unroll 1
            for (int s = 0; s < 8; s++) {
                if (ssidx[s] == step) {
                    out[s * B_POINTS + p0] = oA;
                    out[s * B_POINTS + p1] = oB;
                }
            }
        }
    }
}

extern "C" void kernel_launch(void* const* d_in, const int* in_sizes, int n_in,
                              void* d_out, int out_size)
{
    const float* x      = (const float*)d_in[0];
    const float* samples= (const float*)d_in[1];
    const float* w1     = (const float*)d_in[2];
    const float* b1     = (const float*)d_in[3];
    const float* w2     = (const float*)d_in[4];
    const float* b2     = (const float*)d_in[5];
    const float* w3     = (const float*)d_in[6];
    const float* b3     = (const float*)d_in[7];
    const float* w_out  = (const float*)d_in[8];
    const float* b_out  = (const float*)d_in[9];
    float* out = (float*)d_out;

    ode_rk4_kernel<<<NBLOCKS, NTHREADS>>>(x, samples, w1, b1, w2, b2, w3, b3,
                                          w_out, b_out, out);
}